// round 17
// baseline (speedup 1.0000x reference)
#include <cuda_runtime.h>
#include <cuda_fp16.h>
#include <math.h>
#include <stdint.h>

// ---------------------------------------------------------------------------
// UnifiedAttentionAggregator — fp16 HMMA, persistent CTAs, register epilogue
//   C[N,256] = feats @ [W_V | W_U] (cols permuted: warp-local V/U pairing)
// ---------------------------------------------------------------------------

#define N_INST 524288
#define NF     256
#define L_DIM  128
#define NBAGS  4096
#define NTILES (N_INST / 128)

// smem layout (bytes)
#define OFF_WINS 0                          // 256 f32
#define OFF_BV   1024                       // 128 f32
#define OFF_BU   1536
#define OFF_WA   2048
#define OFF_RED  2560                       // red[4][128] f32 = 2048
#define OFF_A    4608
#define A_STRIDE 144
#define A_BUF    (128 * A_STRIDE)           // 18432
#define OFF_B    (OFF_A + 2 * A_BUF)        // 41472
#define SM_TOTAL (OFF_B + 256 * 528)        // 176640

__device__ float g_scores[N_INST];
__device__ int   g_offs[NBAGS + 1];
__device__ __align__(16) __half g_Wh[NF * 256];  // [k][n'] fp16, cols permuted

// ---- helpers --------------------------------------------------------------
__device__ __forceinline__ uint32_t smem_u32(const void* p) {
    uint32_t a;
    asm("{ .reg .u64 t; cvta.to.shared.u64 t, %1; cvt.u32.u64 %0, t; }" : "=r"(a) : "l"(p));
    return a;
}
__device__ __forceinline__ uint32_t cvt_h2(float lo, float hi) {
    uint32_t d;
    asm("cvt.rn.f16x2.f32 %0, %1, %2;" : "=r"(d) : "f"(hi), "f"(lo));
    return d;
}
__device__ __forceinline__ void ldsm4(uint32_t* r, uint32_t addr) {
    asm volatile("ldmatrix.sync.aligned.m8n8.x4.shared.b16 {%0,%1,%2,%3}, [%4];"
                 : "=r"(r[0]), "=r"(r[1]), "=r"(r[2]), "=r"(r[3]) : "r"(addr));
}
__device__ __forceinline__ void ldsm4t(uint32_t* r, uint32_t addr) {
    asm volatile("ldmatrix.sync.aligned.m8n8.x4.trans.shared.b16 {%0,%1,%2,%3}, [%4];"
                 : "=r"(r[0]), "=r"(r[1]), "=r"(r[2]), "=r"(r[3]) : "r"(addr));
}
__device__ __forceinline__ void mma16816(float* c, const uint32_t* a,
                                         uint32_t b0, uint32_t b1) {
    asm volatile(
        "mma.sync.aligned.m16n8k16.row.col.f32.f16.f16.f32 "
        "{%0,%1,%2,%3},{%4,%5,%6,%7},{%8,%9},{%0,%1,%2,%3};"
        : "+f"(c[0]), "+f"(c[1]), "+f"(c[2]), "+f"(c[3])
        : "r"(a[0]), "r"(a[1]), "r"(a[2]), "r"(a[3]), "r"(b0), "r"(b1));
}

// ---------------------------------------------------------------------------
// Kernel 0a: bag-offset scan, shfl-based
// ---------------------------------------------------------------------------
__global__ void scan_kernel(const int* __restrict__ sz32) {
    __shared__ int wsum[32];
    const int t = threadIdx.x, lane = t & 31, w = t >> 5;
    const int stride = (sz32[1] == 0) ? 2 : 1;  // int64 storage detection

    int v[4];
    int s = 0;
#pragma unroll
    for (int j = 0; j < 4; ++j) {
        v[j] = sz32[(4 * t + j) * stride];
        s += v[j];
    }
    const int own = s;
#pragma unroll
    for (int d = 1; d < 32; d <<= 1) {
        int x = __shfl_up_sync(0xffffffffu, s, d);
        if (lane >= d) s += x;
    }
    if (lane == 31) wsum[w] = s;
    __syncthreads();
    if (w == 0) {
        int x = wsum[lane];
#pragma unroll
        for (int d = 1; d < 32; d <<= 1) {
            int y = __shfl_up_sync(0xffffffffu, x, d);
            if (lane >= d) x += y;
        }
        wsum[lane] = x;
    }
    __syncthreads();
    int run = (w ? wsum[w - 1] : 0) + s - own;  // exclusive prefix
#pragma unroll
    for (int j = 0; j < 4; ++j) {
        g_offs[4 * t + j] = run;
        run += v[j];
    }
    if (t == 1023) g_offs[NBAGS] = run;
}

// ---------------------------------------------------------------------------
// Kernel 0b: W -> fp16 [k][n'], n' permuted so warp wn (n' in [64wn,64wn+64))
// holds V l-block [32wn,32wn+32) in its low 32 cols and U same l in high 32.
// ---------------------------------------------------------------------------
__global__ void wsplit_kernel(const float* __restrict__ W_V,
                              const float* __restrict__ W_U) {
    const int idx = blockIdx.x * 1024 + threadIdx.x;
    const int k = idx >> 8, np = idx & 255;
    const int g = np >> 6, sub = np & 63;
    const int l = g * 32 + (sub & 31);
    float w = (sub < 32) ? W_V[k * L_DIM + l] : W_U[k * L_DIM + l];
    g_Wh[idx] = __float2half_rn(w);
}

// ---------------------------------------------------------------------------
// Kernel 1: persistent HMMA GEMM. Block 512 thr (16 warps 4x4), warp 32x64.
// B (256k x 256n') resident once per CTA; A double-buffered per chunk.
// ---------------------------------------------------------------------------
__global__ __launch_bounds__(512, 1) void gemm_kernel(
    const float* __restrict__ feats,
    const float* __restrict__ W_ins, const float* __restrict__ b_ins,
    const float* __restrict__ b_V, const float* __restrict__ b_U,
    const float* __restrict__ w_att,
    float* __restrict__ out_inst)
{
    extern __shared__ __align__(16) unsigned char sm[];
    const int tid  = threadIdx.x;
    const int wid  = tid >> 5;
    const int lane = tid & 31;
    const int wm   = wid & 3;    // M-warp (32 rows)
    const int wn   = wid >> 2;   // N-warp (64 permuted cols)
    const uint32_t smb = smem_u32(sm);
    const float bins = __ldg(b_ins);

    // consts + B, once per CTA
    if (tid < 256) ((float*)(sm + OFF_WINS))[tid] = W_ins[tid];
    if (tid < L_DIM) {
        ((float*)(sm + OFF_BV))[tid] = b_V[tid];
        ((float*)(sm + OFF_BU))[tid] = b_U[tid];
        ((float*)(sm + OFF_WA))[tid] = w_att[tid];
    }
#pragma unroll
    for (int i = 0; i < 16; ++i) {
        const int idx = tid + 512 * i;           // 8192 uint4
        const int kk = idx >> 5, q = idx & 31;
        *(uint4*)(sm + OFF_B + kk * 528 + q * 16) = __ldg(((const uint4*)g_Wh) + idx);
    }
    __syncthreads();
    const float* Wins_s = (const float*)(sm + OFF_WINS);
    const float* bV_s   = (const float*)(sm + OFF_BV);
    const float* bU_s   = (const float*)(sm + OFF_BU);
    const float* wa_s   = (const float*)(sm + OFF_WA);
    float* red          = (float*)(sm + OFF_RED);   // [4][128]

    const int arow = tid >> 2;         // 0..127
    const int akq  = tid & 3;          // 16-k quarter
    unsigned char* aDst0 = sm + OFF_A + arow * A_STRIDE + akq * 32;

    const uint32_t aBase = smb + OFF_A + (uint32_t)(wm * 32 + (lane & 15)) * A_STRIDE
                         + (uint32_t)(lane >> 4) * 16;
    const uint32_t bBase = smb + OFF_B + (uint32_t)(lane & 15) * 528
                         + (uint32_t)(wn * 64 + (lane >> 4) * 8) * 2;

    const int G = gridDim.x;
    float4 f[4];
    // prologue: first tile, chunk 0
    {
        const float* ap = feats + (size_t)(blockIdx.x * 128 + arow) * NF + akq * 16;
#pragma unroll
        for (int q = 0; q < 4; ++q) f[q] = *(const float4*)(ap + q * 4);
    }

    for (int tile = blockIdx.x; tile < NTILES; tile += G) {
        const int row0 = tile * 128;
        float insp = 0.f;
        float acc[2][8][4];
#pragma unroll
        for (int mt = 0; mt < 2; ++mt)
#pragma unroll
            for (int nf = 0; nf < 8; ++nf)
#pragma unroll
                for (int j = 0; j < 4; ++j) acc[mt][nf][j] = 0.f;

        for (int c = 0; c < 4; ++c) {
            // ---- store chunk c (held in f) into buf[c&1] ----
            {
                unsigned char* dst = aDst0 + (c & 1) * A_BUF;
#pragma unroll
                for (int q = 0; q < 4; ++q) {
                    const int kk = c * 64 + akq * 16 + q * 4;
                    insp += f[q].x * Wins_s[kk]     + f[q].y * Wins_s[kk + 1]
                          + f[q].z * Wins_s[kk + 2] + f[q].w * Wins_s[kk + 3];
                    *(uint2*)(dst + q * 8) =
                        make_uint2(cvt_h2(f[q].x, f[q].y), cvt_h2(f[q].z, f[q].w));
                }
            }
            __syncthreads();

            // ---- prefetch next chunk (or next tile's chunk 0) ----
            if (c < 3) {
                const float* ap = feats + (size_t)(row0 + arow) * NF + (c + 1) * 64 + akq * 16;
#pragma unroll
                for (int q = 0; q < 4; ++q) f[q] = *(const float4*)(ap + q * 4);
            } else if (tile + G < NTILES) {
                const float* ap = feats + (size_t)((tile + G) * 128 + arow) * NF + akq * 16;
#pragma unroll
                for (int q = 0; q < 4; ++q) f[q] = *(const float4*)(ap + q * 4);
            }

            // ---- compute chunk c ----
            const uint32_t aBufc = aBase + (uint32_t)(c & 1) * A_BUF;
#pragma unroll
            for (int kt = 0; kt < 4; ++kt) {
                const uint32_t aAddr = aBufc + kt * 32;
                const uint32_t bAddr = bBase + (uint32_t)(c * 64 + kt * 16) * 528;
                uint32_t Ah[2][4], Bf[4][4];

                ldsm4(Ah[0], aAddr);
                ldsm4(Ah[1], aAddr + 16 * A_STRIDE);
#pragma unroll
                for (int j = 0; j < 4; ++j)
                    ldsm4t(Bf[j], bAddr + j * 32);
#pragma unroll
                for (int mt = 0; mt < 2; ++mt)
#pragma unroll
                    for (int nf = 0; nf < 8; ++nf)
                        mma16816(acc[mt][nf], Ah[mt],
                                 Bf[nf >> 1][(nf & 1) * 2], Bf[nf >> 1][(nf & 1) * 2 + 1]);
            }
        }

        // ---- instance predictions ----
        {
            float p = insp + __shfl_xor_sync(0xffffffffu, insp, 1);
            p += __shfl_xor_sync(0xffffffffu, p, 2);
            if (akq == 0) out_inst[row0 + arow] = p + bins;
        }

        // ---- register epilogue: V = acc[.][0..3], U = acc[.][4..7] (same l) ----
        {
            float part[4] = {0.f, 0.f, 0.f, 0.f};
#pragma unroll
            for (int mt = 0; mt < 2; ++mt)
#pragma unroll
                for (int nf = 0; nf < 4; ++nf)
#pragma unroll
                    for (int e = 0; e < 2; ++e) {
                        const int l = wn * 32 + (lane & 3) * 2 + nf * 8 + e;
                        const float bv = bV_s[l], bu = bU_s[l], wa = wa_s[l];
                        // rows rbase+mt*16 (c[e]) and +8 (c[2+e])
                        float v0 = acc[mt][nf][e]     + bv;
                        float u0 = acc[mt][nf + 4][e] + bu;
                        float v1 = acc[mt][nf][2 + e]     + bv;
                        float u1 = acc[mt][nf + 4][2 + e] + bu;
                        float th0 = 2.f * __fdividef(1.f, 1.f + __expf(-2.f * v0)) - 1.f;
                        float th1 = 2.f * __fdividef(1.f, 1.f + __expf(-2.f * v1)) - 1.f;
                        part[mt * 2]     += th0 * __fdividef(1.f, 1.f + __expf(-u0)) * wa;
                        part[mt * 2 + 1] += th1 * __fdividef(1.f, 1.f + __expf(-u1)) * wa;
                    }
            // sum over the 4 lanes sharing each row (lane&3 = l-subgroups)
#pragma unroll
            for (int d = 1; d <= 2; d <<= 1)
#pragma unroll
                for (int j = 0; j < 4; ++j)
                    part[j] += __shfl_xor_sync(0xffffffffu, part[j], d);
            if ((lane & 3) == 0) {
                const int rbase = wm * 32 + (lane >> 2);
#pragma unroll
                for (int j = 0; j < 4; ++j)          // j = mt*2 + h : row rbase+mt*16+h*8
                    red[wn * 128 + rbase + (j >> 1) * 16 + (j & 1) * 8] = part[j];
            }
        }
        __syncthreads();
        if (tid < 128)
            g_scores[row0 + tid] = red[tid] + red[128 + tid]
                                 + red[256 + tid] + red[384 + tid];
        // next iteration's first __syncthreads() protects red reuse
    }
}

// ---------------------------------------------------------------------------
// Kernel 2: per-bag segmented softmax + weighted sum (C=1).
// (b_att omitted: constant shift cancels in softmax.)
// ---------------------------------------------------------------------------
__global__ void bag_kernel(const float* __restrict__ inst,
                           float* __restrict__ out_bag)
{
    const int b   = blockIdx.x;
    const int tid = threadIdx.x;
    const int s0  = g_offs[b];
    const int s1  = g_offs[b + 1];

    __shared__ float rm[4], re[4], rp[4];

    float m = -3.4e38f;
    for (int i = s0 + tid; i < s1; i += 128) m = fmaxf(m, g_scores[i]);
#pragma unroll
    for (int d = 16; d >= 1; d >>= 1)
        m = fmaxf(m, __shfl_xor_sync(0xffffffffu, m, d));
    if ((tid & 31) == 0) rm[tid >> 5] = m;
    __syncthreads();
    m = fmaxf(fmaxf(rm[0], rm[1]), fmaxf(rm[2], rm[3]));

    float se = 0.f, sp = 0.f;
    for (int i = s0 + tid; i < s1; i += 128) {
        float e = expf(g_scores[i] - m);
        se += e;
        sp += e * inst[i];
    }
#pragma unroll
    for (int d = 16; d >= 1; d >>= 1) {
        se += __shfl_xor_sync(0xffffffffu, se, d);
        sp += __shfl_xor_sync(0xffffffffu, sp, d);
    }
    if ((tid & 31) == 0) { re[tid >> 5] = se; rp[tid >> 5] = sp; }
    __syncthreads();
    if (tid == 0) {
        out_bag[b] = (rp[0] + rp[1] + rp[2] + rp[3]) /
                     (re[0] + re[1] + re[2] + re[3]);
    }
}

// ---------------------------------------------------------------------------
extern "C" void kernel_launch(void* const* d_in, const int* in_sizes, int n_in,
                              void* d_out, int out_size)
{
    const float* feats = (const float*)d_in[0];
    const int*   sz32  = (const int*)d_in[1];
    const float* W_ins = (const float*)d_in[2];
    const float* b_ins = (const float*)d_in[3];
    const float* W_V   = (const float*)d_in[4];
    const float* b_V   = (const float*)d_in[5];
    const float* W_U   = (const float*)d_in[6];
    const float* b_U   = (const float*)d_in[7];
    const float* w_att = (const float*)d_in[8];

    float* out      = (float*)d_out;
    float* out_bag  = out;           // [4096]
    float* out_inst = out + NBAGS;   // [524288]

    int sms = 148;
    cudaDeviceGetAttribute(&sms, cudaDevAttrMultiProcessorCount, 0);
    if (sms > NTILES) sms = NTILES;

    cudaFuncSetAttribute(gemm_kernel, cudaFuncAttributeMaxDynamicSharedMemorySize, SM_TOTAL);

    scan_kernel<<<1, 1024>>>(sz32);
    wsplit_kernel<<<64, 1024>>>(W_V, W_U);
    gemm_kernel<<<sms, 512, SM_TOTAL>>>(feats, W_ins, b_ins, b_V, b_U,
                                        w_att, out_inst);
    bag_kernel<<<NBAGS, 128>>>(out_inst, out_bag);
}